// round 16
// baseline (speedup 1.0000x reference)
#include <cuda_runtime.h>
#include <cuda_fp16.h>
#include <cstdint>

// ---------------------------------------------------------------------------
// CNNInteractLayer — mma.sync fp16 GEMM-factored implementation.
// conv(concat(s_i,q_j)) = conv_s(s_i) + conv_q(q_j) + bias  (conv is linear).
// Per half: Z[2176x3200] = W[2176x512] @ X[512x3200]^T-view on tensor cores,
// single-product fp16 (quantization ~1.4e-4 << 1e-3 gate), fp32 accumulation.
// Then shift-add epilogue + register-tiled high-occupancy pairwise combine.
// ---------------------------------------------------------------------------

#define LSEQ 31
#define DIM 512
#define NROWS 100
#define NCC 600
#define LP 32
#define MTOT 2100
#define MSTR 2176          // 17 * 128
#define NSTR 3200          // 100 rows * 32 = 25 * 128
#define NCH 8              // 512 / 64 k-chunks

typedef unsigned long long ull;

__device__ __half g_Wh[2 * MSTR * DIM];            // [half][m][k]
__device__ __half g_Xh[2 * NSTR * DIM];            // [half][n][k]
__device__ float g_Z[2 * (size_t)MSTR * NSTR];
__device__ float g_bias[NCC];
__device__ float g_A[NROWS * NCC * LP];
__device__ float g_B[NROWS * NCC * LP];

// ---------------- PTX helpers ----------------
__device__ __forceinline__ uint32_t s2u(const void* p) {
    uint32_t a;
    asm("{ .reg .u64 t; cvta.to.shared.u64 t, %1; cvt.u32.u64 %0, t; }"
        : "=r"(a) : "l"(p));
    return a;
}
__device__ __forceinline__ void cp16(uint32_t saddr, const void* gptr) {
    asm volatile("cp.async.cg.shared.global [%0], [%1], 16;"
                 :: "r"(saddr), "l"(gptr));
}
__device__ __forceinline__ void ldsm4(uint32_t* r, uint32_t addr) {
    asm volatile("ldmatrix.sync.aligned.m8n8.x4.shared.b16 {%0,%1,%2,%3}, [%4];"
                 : "=r"(r[0]), "=r"(r[1]), "=r"(r[2]), "=r"(r[3]) : "r"(addr));
}
__device__ __forceinline__ void mma_f16(float* d, const uint32_t* a,
                                        const uint32_t* b) {
    asm volatile(
        "mma.sync.aligned.m16n8k16.row.col.f32.f16.f16.f32 "
        "{%0,%1,%2,%3}, {%4,%5,%6,%7}, {%8,%9}, {%0,%1,%2,%3};"
        : "+f"(d[0]), "+f"(d[1]), "+f"(d[2]), "+f"(d[3])
        : "r"(a[0]), "r"(a[1]), "r"(a[2]), "r"(a[3]), "r"(b[0]), "r"(b[1]));
}
#define SW128(x) ((x) ^ (((x) >> 3) & 0x70))

// ---------------------------------------------------------------------------
// prep: ONE kernel for W gather->fp16, X transpose->fp16, and bias.
// ---------------------------------------------------------------------------
#define NWELEM (2 * MSTR * DIM)
#define NXELEM (2 * NSTR * DIM)

__global__ void prep_kernel(const float* __restrict__ s, const float* __restrict__ q,
                            const float* __restrict__ w2, const float* __restrict__ b2,
                            const float* __restrict__ w3, const float* __restrict__ b3,
                            const float* __restrict__ w4, const float* __restrict__ b4,
                            const float* __restrict__ w5, const float* __restrict__ b5) {
    int idx = blockIdx.x * blockDim.x + threadIdx.x;
    if (idx < NCC) {
        int conv = idx / 150, c = idx - conv * 150;
        const float* bp = (conv == 0) ? b2 : (conv == 1) ? b3 : (conv == 2) ? b4 : b5;
        g_bias[idx] = bp[c];
    }
    if (idx < NWELEM) {
        int h = idx / (MSTR * DIM);
        int rem = idx - h * (MSTR * DIM);
        int m = rem / DIM;
        int d = rem - m * DIM;
        float v = 0.f;
        if (m < MTOT) {
            int conv = (m < 300) ? 0 : (m < 750) ? 1 : (m < 1350) ? 2 : 3;
            int base = (conv == 0) ? 0 : (conv == 1) ? 300 : (conv == 2) ? 750 : 1350;
            int k = conv + 2;
            int mm = m - base;
            int t = mm / 150, c = mm - t * 150;
            const float* w = (conv == 0) ? w2 : (conv == 1) ? w3 : (conv == 2) ? w4 : w5;
            v = w[(c * 1024 + h * DIM + d) * k + t];
        }
        g_Wh[idx] = __float2half(v);
    }
    if (idx < NXELEM) {
        int h = idx / (NSTR * DIM);
        int rem = idx - h * (NSTR * DIM);
        int n = rem / DIM;
        int d = rem - n * DIM;
        int r = n >> 5, l = n & 31;
        const float* x = (h ? q : s);
        float v = (l < LSEQ) ? x[((size_t)r * LSEQ + l) * DIM + d] : 0.f;
        g_Xh[idx] = __float2half(v);
    }
}

// ---------------------------------------------------------------------------
// gemm: 128x128 block tile, 4 warps (2x2, warp tile 64x64), BK=64,
// double-buffered cp.async, SW128 smem rows (128B), 64KB smem -> 2 CTAs/SM.
// ---------------------------------------------------------------------------
#define SM_BUF 32768
#define SM_TOTAL 65536

__global__ void __launch_bounds__(128, 2) gemm_kernel() {
    extern __shared__ char smem[];
    uint32_t sb = s2u(smem);
    int tid = threadIdx.x, wid = tid >> 5, lane = tid & 31;
    int bx = blockIdx.x, by = blockIdx.y, h = blockIdx.z;

    const __half* Wh = g_Wh + ((size_t)h * MSTR + by * 128) * DIM;
    const __half* Xh = g_Xh + ((size_t)h * NSTR + bx * 128) * DIM;
    const __half* mats[2] = {Wh, Xh};

    int wm0 = (wid >> 1) * 64;
    int wn0 = (wid & 1) * 64;

    float acc[4][8][4];
#pragma unroll
    for (int mt = 0; mt < 4; mt++)
#pragma unroll
        for (int nt = 0; nt < 8; nt++)
#pragma unroll
            for (int i = 0; i < 4; i++) acc[mt][nt][i] = 0.f;

#define STAGE(cc)                                                              \
    {                                                                          \
        int koff = (cc) * 64;                                                  \
        uint32_t bb = sb + ((cc) & 1) * SM_BUF;                                \
        _Pragma("unroll")                                                      \
        for (int rep = 0; rep < 16; rep++) {                                   \
            int cid = rep * 128 + tid;                                         \
            int mat = cid >> 10;                                               \
            int r = (cid >> 3) & 127;                                          \
            int kc = cid & 7;                                                  \
            cp16(bb + mat * 16384 + SW128(r * 128 + kc * 16),                  \
                 mats[mat] + (size_t)r * DIM + koff + kc * 8);                 \
        }                                                                      \
        asm volatile("cp.async.commit_group;");                                \
    }

    STAGE(0);
    for (int c = 0; c < NCH; c++) {
        if (c + 1 < NCH) {
            STAGE(c + 1);
            asm volatile("cp.async.wait_group 1;");
        } else {
            asm volatile("cp.async.wait_group 0;");
        }
        __syncthreads();

        uint32_t sbAh = sb + (c & 1) * SM_BUF;
        uint32_t sbBh = sbAh + 16384;
#pragma unroll
        for (int ks = 0; ks < 4; ks++) {
            uint32_t ah[4][4], bh[4][4];
#pragma unroll
            for (int mt = 0; mt < 4; mt++) {
                int row = wm0 + mt * 16 + (lane & 15);
                int colh = lane >> 4;
                uint32_t off = SW128(row * 128 + (ks * 2 + colh) * 16);
                ldsm4(ah[mt], sbAh + off);
            }
#pragma unroll
            for (int bt = 0; bt < 4; bt++) {
                int n = wn0 + bt * 16 + ((lane >> 4) << 3) + (lane & 7);
                int khalf = (lane >> 3) & 1;
                uint32_t off = SW128(n * 128 + ks * 32 + khalf * 16);
                ldsm4(bh[bt], sbBh + off);
            }
#pragma unroll
            for (int mt = 0; mt < 4; mt++)
#pragma unroll
                for (int nt = 0; nt < 8; nt++)
                    mma_f16(acc[mt][nt], ah[mt], bh[nt >> 1] + (nt & 1) * 2);
        }
        __syncthreads();
    }
#undef STAGE

    int gr = lane >> 2, gc = (lane & 3) * 2;
    float* Zp = g_Z + (size_t)h * MSTR * NSTR;
#pragma unroll
    for (int mt = 0; mt < 4; mt++) {
        int row0 = by * 128 + wm0 + mt * 16 + gr;
#pragma unroll
        for (int nt = 0; nt < 8; nt++) {
            int col = bx * 128 + wn0 + nt * 8 + gc;
            float2 lo = make_float2(acc[mt][nt][0], acc[mt][nt][1]);
            float2 hi = make_float2(acc[mt][nt][2], acc[mt][nt][3]);
            *(float2*)(Zp + (size_t)row0 * NSTR + col) = lo;
            *(float2*)(Zp + (size_t)(row0 + 8) * NSTR + col) = hi;
        }
    }
}

// ---------------------------------------------------------------------------
// epilogue: Y[h][r][conv*150+c][l] = sum_t Z[h][base+t*150+c][r*32 + l+t-pad]
// 2-row ILP per thread (c and c+75).
// ---------------------------------------------------------------------------
template <int CONV>
__device__ __forceinline__ void epi_body(int r, int h) {
    const int k = CONV + 2;
    const int pad = (CONV >= 2) ? 2 : 1;
    const int base = (CONV == 0) ? 0 : (CONV == 1) ? 300 : (CONV == 2) ? 750 : 1350;
    const float* Zp = g_Z + (size_t)h * MSTR * NSTR + r * 32;
    float* out = (h ? g_B : g_A) + (size_t)r * NCC * LP + CONV * 150 * LP;
    for (int i = threadIdx.x; i < 75 * 32; i += 256) {
        int c = i >> 5, l = i & 31;
        float v0 = -1e30f, v1 = -1e30f;
        if (l < LSEQ) {
            v0 = 0.f; v1 = 0.f;
#pragma unroll
            for (int t = 0; t < k; t++) {
                int lp = l + t - pad;
                if (lp >= 0 && lp < 32) {
                    v0 += __ldg(Zp + (size_t)(base + t * 150 + c) * NSTR + lp);
                    v1 += __ldg(Zp + (size_t)(base + t * 150 + c + 75) * NSTR + lp);
                }
            }
        }
        out[c * LP + l] = v0;
        out[(c + 75) * LP + l] = v1;
    }
}

__global__ void epilogue_kernel() {
    int r = blockIdx.x, h = blockIdx.z;
    switch (blockIdx.y) {
        case 0: epi_body<0>(r, h); break;
        case 1: epi_body<1>(r, h); break;
        case 2: epi_body<2>(r, h); break;
        case 3: epi_body<3>(r, h); break;
    }
}

// ---------------------------------------------------------------------------
// combine: register-tiled pair combine, high occupancy. Block = (pair-tile,
// cc-slab of 25); 36KB smem -> 6 CTAs/SM (75% occ). Thread owns (cci, ii),
// accumulates m[5] over jj (sB reads broadcast across same-cci threads).
// out_ch = max(0, max_l(A+B) + bias).
// ---------------------------------------------------------------------------
#define CSLAB 25
#define NSLAB (NCC / CSLAB)              // 24
#define CROWPAD 36                       // 16B-aligned, conflict-free phases
#define CROWSZ (CSLAB * CROWPAD)         // 900 floats per staged row
#define CMB_SMEM (2 * 5 * CROWSZ * 4)    // 36000 bytes

__global__ void __launch_bounds__(128) combine_kernel(float* __restrict__ out) {
    extern __shared__ float cs[];
    float* sA = cs;                      // [5][CROWSZ]
    float* sB = cs + 5 * CROWSZ;

    int blk = blockIdx.x;                // 0..99 pair tile
    int sl = blockIdx.y;                 // 0..23 cc slab
    int b = blk / 25;
    int rem = blk - b * 25;
    int ig = rem / 5, jg = rem - (rem / 5) * 5;
    int b25 = b * 25;
    int tid = threadIdx.x;

    // stage 5 A rows + 5 B rows for this slab (float4 both sides)
    for (int idx = tid; idx < 10 * CSLAB * 8; idx += 128) {
        int row = idx / (CSLAB * 8);     // 0..9 (0-4: A, 5-9: B)
        int rest = idx - row * (CSLAB * 8);
        int cc = rest >> 3, l4 = rest & 7;
        int isB = row >= 5;
        int rloc = isB ? row - 5 : row;
        const float* gsrc = isB ? g_B : g_A;
        int grow = b25 + (isB ? jg : ig) * 5 + rloc;
        float4 v = *(const float4*)(gsrc + ((size_t)grow * NCC + sl * CSLAB + cc) * LP
                                    + l4 * 4);
        float* d = (isB ? sB : sA) + rloc * CROWSZ + cc * CROWPAD + l4 * 4;
        *(float4*)d = v;
    }
    __syncthreads();

    // thread = (ii, cci): ii = tid/25, cci = tid%25; 125 active threads
    if (tid < 125) {
        int ii = tid / CSLAB;
        int cci = tid - ii * CSLAB;
        const float4* ar = (const float4*)(sA + ii * CROWSZ + cci * CROWPAD);
        float m[5];
#pragma unroll
        for (int jj = 0; jj < 5; jj++) m[jj] = -3.0e38f;
#pragma unroll
        for (int l4 = 0; l4 < 8; l4++) {
            float4 a = ar[l4];
#pragma unroll
            for (int jj = 0; jj < 5; jj++) {
                float4 bb = *(const float4*)(sB + jj * CROWSZ + cci * CROWPAD
                                             + l4 * 4);
                float mm = fmaxf(fmaxf(a.x + bb.x, a.y + bb.y),
                                 fmaxf(a.z + bb.z, a.w + bb.w));
                m[jj] = fmaxf(m[jj], mm);
            }
        }
        int cc = sl * CSLAB + cci;
        float bias = g_bias[cc];
        int conv = cc / 150;
        int c = cc - conv * 150;
        int base_off = (c < 75) ? (conv * 75 + c) : (750000 + conv * 75 + (c - 75));
        int prow = b * 625 + (ig * 5 + ii) * 25 + jg * 5;
#pragma unroll
        for (int jj = 0; jj < 5; jj++) {
            float v = fmaxf(0.f, m[jj] + bias);
            out[(prow + jj) * 300 + base_off] = v;
        }
    }
}

// ---------------------------------------------------------------------------
extern "C" void kernel_launch(void* const* d_in, const int* in_sizes, int n_in,
                              void* d_out, int out_size) {
    const float* s  = (const float*)d_in[0];
    const float* q  = (const float*)d_in[1];
    const float* w2 = (const float*)d_in[2];
    const float* b2 = (const float*)d_in[3];
    const float* w3 = (const float*)d_in[4];
    const float* b3 = (const float*)d_in[5];
    const float* w4 = (const float*)d_in[6];
    const float* b4 = (const float*)d_in[7];
    const float* w5 = (const float*)d_in[8];
    const float* b5 = (const float*)d_in[9];
    float* out = (float*)d_out;

    cudaFuncSetAttribute(gemm_kernel, cudaFuncAttributeMaxDynamicSharedMemorySize,
                         SM_TOTAL);
    cudaFuncSetAttribute(combine_kernel, cudaFuncAttributeMaxDynamicSharedMemorySize,
                         CMB_SMEM);

    prep_kernel<<<(NXELEM + 255) / 256, 256>>>(s, q, w2, b2, w3, b3, w4, b4, w5, b5);
    gemm_kernel<<<dim3(NSTR / 128, MSTR / 128, 2), 128, SM_TOTAL>>>();
    epilogue_kernel<<<dim3(NROWS, 4, 2), 256>>>();
    combine_kernel<<<dim3(100, NSLAB), 128, CMB_SMEM>>>(out);
}